// round 1
// baseline (speedup 1.0000x reference)
#include <cuda_runtime.h>

// Problem constants
#define H   8
#define M   1024
#define D   64
#define B   8
#define L   2048
#define N   16384      // B*L tokens per head
#define TM  128        // codebook rows per smem tile

// d_out packing (float32): z_q | vq_loss | indices | new_codebooks
#define ZQ_OFF   ((size_t)0)
#define LOSS_OFF ((size_t)8388608)
#define IDX_OFF  ((size_t)8388609)
#define CB_OFF   ((size_t)8519681)

// Scratch (no allocations allowed -> __device__ globals)
__device__ float g_sums[H * M * D];
__device__ float g_counts[H * M];
__device__ float g_loss;

// ---------------------------------------------------------------------------
// packed f32x2 helpers (Blackwell FFMA2 path, only reachable via PTX)
// ---------------------------------------------------------------------------
__device__ __forceinline__ unsigned long long ffma2(unsigned long long a,
                                                    unsigned long long b,
                                                    unsigned long long c) {
    unsigned long long d;
    asm("fma.rn.f32x2 %0, %1, %2, %3;" : "=l"(d) : "l"(a), "l"(b), "l"(c));
    return d;
}
__device__ __forceinline__ unsigned long long pack2(float lo, float hi) {
    unsigned long long r;
    asm("mov.b64 %0, {%1, %2};" : "=l"(r) : "f"(lo), "f"(hi));
    return r;
}
__device__ __forceinline__ float2 unpack2(unsigned long long v) {
    float lo, hi;
    asm("mov.b64 {%0, %1}, %2;" : "=f"(lo), "=f"(hi) : "l"(v));
    return make_float2(lo, hi);
}

// ---------------------------------------------------------------------------
// Kernel 0: zero the scratch accumulators
// ---------------------------------------------------------------------------
__global__ void zero_kernel() {
    int i = blockIdx.x * 256 + threadIdx.x;
    if (i < H * M * D) g_sums[i] = 0.0f;
    if (i < H * M)     g_counts[i] = 0.0f;
    if (i == 0)        g_loss = 0.0f;
}

// ---------------------------------------------------------------------------
// Kernel 1: per-token argmax over 1024 codes + z_q write + loss + segment sums
// One thread = one token n of head h. z row held as 32 packed f32x2 registers.
// Codebooks streamed through shared memory in TM-row tiles; all lanes read the
// same codebook element -> broadcast, conflict-free.
// ---------------------------------------------------------------------------
__global__ __launch_bounds__(256, 2)
void vq_main(const float* __restrict__ z, const float* __restrict__ cb,
             float* __restrict__ out) {
    __shared__ float s_cb[TM * D];
    __shared__ float s_red[8];

    const int h = blockIdx.y;
    const int n = blockIdx.x * 256 + threadIdx.x;
    const int b = n >> 11;          // n / L
    const int l = n & (L - 1);      // n % L

    // z[b, h*64 + k, l]; stride L between consecutive k. Coalesced across lanes.
    const size_t zbase = ((size_t)b * 512 + (size_t)h * 64) * (size_t)L + (size_t)l;

    unsigned long long z2[32];
#pragma unroll
    for (int j = 0; j < 32; j++) {
        float lo = __ldg(z + zbase + (size_t)(2 * j) * L);
        float hi = __ldg(z + zbase + (size_t)(2 * j + 1) * L);
        z2[j] = pack2(lo, hi);
    }

    const float* cbh = cb + (size_t)h * M * D;
    float best = -1e30f;
    int bidx = 0;

    for (int t = 0; t < M / TM; t++) {
        __syncthreads();
        // load tile: TM*D = 8192 floats = 2048 float4, 8 per thread
        const float4* src = (const float4*)(cbh + (size_t)t * TM * D);
        float4* dst = (float4*)s_cb;
#pragma unroll
        for (int j = 0; j < 8; j++)
            dst[threadIdx.x + j * 256] = src[threadIdx.x + j * 256];
        __syncthreads();

#pragma unroll 1
        for (int m = 0; m < TM; m++) {
            const ulonglong2* row = (const ulonglong2*)(s_cb + m * D);
            unsigned long long a0 = 0ull, a1 = 0ull, a2 = 0ull, a3 = 0ull;
#pragma unroll
            for (int j = 0; j < 8; j++) {
                ulonglong2 c0 = row[2 * j];
                ulonglong2 c1 = row[2 * j + 1];
                a0 = ffma2(z2[4 * j + 0], c0.x, a0);
                a1 = ffma2(z2[4 * j + 1], c0.y, a1);
                a2 = ffma2(z2[4 * j + 2], c1.x, a2);
                a3 = ffma2(z2[4 * j + 3], c1.y, a3);
            }
            float2 f0 = unpack2(a0), f1 = unpack2(a1);
            float2 f2 = unpack2(a2), f3 = unpack2(a3);
            float sim = ((f0.x + f0.y) + (f1.x + f1.y)) +
                        ((f2.x + f2.y) + (f3.x + f3.y));
            int mg = t * TM + m;
            if (sim > best) { best = sim; bidx = mg; }   // strict '>' keeps first index on ties
        }
    }

    // Epilogue: winner row (L2-resident), z_q write, loss, segment sums
    const float* crow = cbh + (size_t)bidx * D;
    const int sumbase = (h * M + bidx) * D;
    float lsum = 0.0f;
#pragma unroll
    for (int j = 0; j < 32; j++) {
        float2 zv = unpack2(z2[j]);
        float c0 = __ldg(crow + 2 * j);
        float c1 = __ldg(crow + 2 * j + 1);
        out[ZQ_OFF + zbase + (size_t)(2 * j) * L] = c0;
        out[ZQ_OFF + zbase + (size_t)(2 * j + 1) * L] = c1;
        float d0 = zv.x - c0, d1 = zv.y - c1;
        lsum += d0 * d0 + d1 * d1;
        atomicAdd(&g_sums[sumbase + 2 * j], zv.x);
        atomicAdd(&g_sums[sumbase + 2 * j + 1], zv.y);
    }
    atomicAdd(&g_counts[h * M + bidx], 1.0f);

    // indices_out[b, h, l] as float
    out[IDX_OFF + ((size_t)b * H + (size_t)h) * (size_t)L + (size_t)l] = (float)bidx;

    // block-reduce loss -> one atomic per block
#pragma unroll
    for (int o = 16; o > 0; o >>= 1)
        lsum += __shfl_xor_sync(0xffffffffu, lsum, o);
    if ((threadIdx.x & 31) == 0) s_red[threadIdx.x >> 5] = lsum;
    __syncthreads();
    if (threadIdx.x == 0) {
        float t = 0.0f;
#pragma unroll
        for (int w = 0; w < 8; w++) t += s_red[w];
        atomicAdd(&g_loss, t);
    }
}

// ---------------------------------------------------------------------------
// Kernel 2: slerp + rms_norm codebook EMA update (1 warp per code), and the
// final vq_loss scalar.
// ---------------------------------------------------------------------------
__global__ void vq_update(const float* __restrict__ cb, float* __restrict__ out) {
    if (blockIdx.x == 0 && threadIdx.x == 0) {
        // vq_loss = codebook_loss + 0.25*commitment_loss = 1.25 * MSE
        out[LOSS_OFF] = 1.25f * g_loss * (1.0f / 8388608.0f);
    }

    const int code = blockIdx.x * 8 + (threadIdx.x >> 5);  // 8 warps / block
    const int lane = threadIdx.x & 31;
    if (code >= H * M) return;

    const float* old = cb + (size_t)code * D;
    float o0 = old[lane];
    float o1 = old[lane + 32];
    float cnt = g_counts[code];
    float r0, r1;

    if (cnt > 0.0f) {
        float m0 = g_sums[code * D + lane] / cnt;
        float m1 = g_sums[code * D + lane + 32] / cnt;

        float dot = m0 * o0 + m1 * o1;
        float nl  = m0 * m0 + m1 * m1;
        float nh  = o0 * o0 + o1 * o1;
#pragma unroll
        for (int o = 16; o > 0; o >>= 1) {
            dot += __shfl_xor_sync(0xffffffffu, dot, o);
            nl  += __shfl_xor_sync(0xffffffffu, nl,  o);
            nh  += __shfl_xor_sync(0xffffffffu, nh,  o);
        }
        float cosv = dot / fmaxf(sqrtf(nl) * sqrtf(nh), 1e-8f);
        cosv = fminf(fmaxf(cosv, (float)(-1.0 + 1e-7)), (float)(1.0 - 1e-7));
        float omega = acosf(cosv);
        float so = sinf(omega);
        float wl = sinf(0.01f * omega);   // (1 - decay) * omega
        float wh = sinf(0.99f * omega);   // decay * omega
        r0 = (m0 * wl + o0 * wh) / so;
        r1 = (m1 * wl + o1 * wh) / so;

        float ss = r0 * r0 + r1 * r1;
#pragma unroll
        for (int o = 16; o > 0; o >>= 1)
            ss += __shfl_xor_sync(0xffffffffu, ss, o);
        float inv = 1.0f / sqrtf(ss * (1.0f / 64.0f) + 1.1920929e-07f);
        r0 *= inv;
        r1 *= inv;
    } else {
        r0 = o0;
        r1 = o1;
    }

    out[CB_OFF + (size_t)code * D + lane]      = r0;
    out[CB_OFF + (size_t)code * D + lane + 32] = r1;
}

// ---------------------------------------------------------------------------
extern "C" void kernel_launch(void* const* d_in, const int* in_sizes, int n_in,
                              void* d_out, int out_size) {
    const float* z  = (const float*)d_in[0];   // [8, 512, 2048]
    const float* cb = (const float*)d_in[1];   // [8, 1024, 64]
    float* out = (float*)d_out;

    zero_kernel<<<(H * M * D + 255) / 256, 256>>>();

    dim3 grid(N / 256, H);
    vq_main<<<grid, 256>>>(z, cb, out);

    vq_update<<<H * M / 8, 256>>>(cb, out);
}

// round 2
// speedup vs baseline: 1.4204x; 1.4204x over previous
#include <cuda_runtime.h>

// Problem constants
#define H    8
#define M    1024
#define D    64
#define B    8
#define L    2048
#define NTOK 16384     // B*L tokens per head
#define TOK  128       // tokens per block
#define CHUNK 128      // codes per smem chunk

// d_out packing (float32): z_q | vq_loss | indices | new_codebooks
#define ZQ_OFF   ((size_t)0)
#define LOSS_OFF ((size_t)8388608)
#define IDX_OFF  ((size_t)8388609)
#define CB_OFF   ((size_t)8519681)

typedef unsigned long long u64;

// Scratch (no allocations allowed -> __device__ globals). Zero at module load;
// re-zeroed at the TAIL of every kernel_launch so each call sees clean state.
__device__ float g_sums[H * M * D];
__device__ float g_counts[H * M];
__device__ float g_loss;

// ---------------------------------------------------------------------------
// packed f32x2 helpers (Blackwell FFMA2 path, only reachable via PTX)
// ---------------------------------------------------------------------------
__device__ __forceinline__ u64 ffma2(u64 a, u64 b, u64 c) {
    u64 d;
    asm("fma.rn.f32x2 %0, %1, %2, %3;" : "=l"(d) : "l"(a), "l"(b), "l"(c));
    return d;
}
__device__ __forceinline__ u64 pack2(float lo, float hi) {
    u64 r;
    asm("mov.b64 %0, {%1, %2};" : "=l"(r) : "f"(lo), "f"(hi));
    return r;
}
__device__ __forceinline__ float2 unpack2(u64 v) {
    float lo, hi;
    asm("mov.b64 {%0, %1}, %2;" : "=f"(lo), "=f"(hi) : "l"(v));
    return make_float2(lo, hi);
}

// ---------------------------------------------------------------------------
struct Smem {
    float zs[D][TOK];      // z tile, k-major:     32 KB
    float cs[D][CHUNK];    // codebook chunk, k-major: 32 KB
    int   sidx[TOK];
    float red[8];
};

// ---------------------------------------------------------------------------
// Kernel: zero the scratch accumulators (runs at TAIL of each call)
// ---------------------------------------------------------------------------
__global__ void zero_kernel() {
    int i = blockIdx.x * 256 + threadIdx.x;
    if (i < H * M * D) g_sums[i] = 0.0f;
    if (i < H * M)     g_counts[i] = 0.0f;
    if (i == 0)        g_loss = 0.0f;
}

// ---------------------------------------------------------------------------
// Main kernel: register-blocked sim GEMM + argmax + fused epilogue.
// Block: 128 tokens x 1024 codes (8 chunks of 128). Thread: 8 tokens x 8 codes,
// accumulators packed f32x2 over code pairs.
// ---------------------------------------------------------------------------
__global__ __launch_bounds__(256, 2)
void vq_main(const float* __restrict__ z, const float* __restrict__ cb,
             float* __restrict__ out) {
    extern __shared__ char smem_raw[];
    Smem& s = *reinterpret_cast<Smem*>(smem_raw);

    const int tid = threadIdx.x;
    const int h   = blockIdx.y;
    const int n0  = blockIdx.x * TOK;
    const int b   = n0 >> 11;           // n0 / L
    const int l0  = n0 & (L - 1);       // n0 % L  (multiple of 128 -> 16B aligned)
    const int tx  = tid & 15;           // code group 0..15
    const int ty  = tid >> 4;           // token group 0..15

    // ---- load z tile [64 k x 128 tok], coalesced float4 ----
    const size_t zbase = ((size_t)(b * 512 + h * 64)) * (size_t)L + (size_t)l0;
#pragma unroll
    for (int r = 0; r < 8; r++) {
        int f  = tid + 256 * r;         // float4 id, 2048 total
        int k  = f >> 5;
        int t4 = f & 31;
        float4 v = *(const float4*)(z + zbase + (size_t)k * L + (size_t)t4 * 4);
        *(float4*)&s.zs[k][t4 * 4] = v;
    }

    float best[8];
    int   bidx[8];
#pragma unroll
    for (int t = 0; t < 8; t++) { best[t] = -3.4e38f; bidx[t] = 0; }

    const float* cbh = cb + (size_t)h * M * D;

    for (int cc = 0; cc < M / CHUNK; cc++) {
        __syncthreads();   // protect cs from previous chunk's readers (also covers zs load)
        // ---- load codebook chunk transposed into cs[k][m] ----
        // thread: row m = tid&127, k-half kh = tid>>7; lane streams its own row.
        {
            int m  = tid & 127;
            int kh = tid >> 7;
            const float* src = cbh + (size_t)(cc * CHUNK + m) * D + kh * 32;
#pragma unroll
            for (int q = 0; q < 8; q++) {
                float4 v = *(const float4*)(src + q * 4);
                int k0 = kh * 32 + q * 4;
                s.cs[k0 + 0][m] = v.x;
                s.cs[k0 + 1][m] = v.y;
                s.cs[k0 + 2][m] = v.z;
                s.cs[k0 + 3][m] = v.w;
            }
        }
        __syncthreads();

        u64 acc[8][4];
#pragma unroll
        for (int t = 0; t < 8; t++)
#pragma unroll
            for (int j = 0; j < 4; j++) acc[t][j] = 0ull;

#pragma unroll 4
        for (int k = 0; k < D; k++) {
            float4 za = *(const float4*)&s.zs[k][ty * 8];
            float4 zb = *(const float4*)&s.zs[k][ty * 8 + 4];
            ulonglong2 c01 = *(const ulonglong2*)&s.cs[k][tx * 8];
            ulonglong2 c23 = *(const ulonglong2*)&s.cs[k][tx * 8 + 4];
            const u64 cp0 = c01.x, cp1 = c01.y, cp2 = c23.x, cp3 = c23.y;
            float zv[8] = {za.x, za.y, za.z, za.w, zb.x, zb.y, zb.z, zb.w};
#pragma unroll
            for (int t = 0; t < 8; t++) {
                u64 zd = pack2(zv[t], zv[t]);
                acc[t][0] = ffma2(zd, cp0, acc[t][0]);
                acc[t][1] = ffma2(zd, cp1, acc[t][1]);
                acc[t][2] = ffma2(zd, cp2, acc[t][2]);
                acc[t][3] = ffma2(zd, cp3, acc[t][3]);
            }
        }

        const int mbase = cc * CHUNK + tx * 8;
#pragma unroll
        for (int t = 0; t < 8; t++) {
#pragma unroll
            for (int j = 0; j < 4; j++) {
                float2 v = unpack2(acc[t][j]);
                if (v.x > best[t]) { best[t] = v.x; bidx[t] = mbase + 2 * j; }
                if (v.y > best[t]) { best[t] = v.y; bidx[t] = mbase + 2 * j + 1; }
            }
        }
    }

    // ---- argmax reduction across the 16 code-lanes (tx); first-index tie-break ----
#pragma unroll
    for (int t = 0; t < 8; t++) {
#pragma unroll
        for (int off = 1; off < 16; off <<= 1) {
            float ob = __shfl_xor_sync(0xffffffffu, best[t], off);
            int   oi = __shfl_xor_sync(0xffffffffu, bidx[t], off);
            if (ob > best[t] || (ob == best[t] && oi < bidx[t])) {
                best[t] = ob; bidx[t] = oi;
            }
        }
        if (tx == 0) s.sidx[ty * 8 + t] = bidx[t];
    }
    __syncthreads();

    // ---- epilogue: indices, counts, z_q, loss, segment sums ----
    if (tid < TOK) {
        int m = s.sidx[tid];
        out[IDX_OFF + ((size_t)b * H + (size_t)h) * (size_t)L + (size_t)(l0 + tid)] = (float)m;
        atomicAdd(&g_counts[h * M + m], 1.0f);
    }

    float lsum = 0.0f;
#pragma unroll
    for (int i = 0; i < 32; i++) {
        int e = i * 256 + tid;          // 8192 elements: (k, tok)
        int k = e >> 7;
        int t = e & 127;
        int m = s.sidx[t];
        float c  = __ldg(cbh + (size_t)m * D + k);
        float zv = s.zs[k][t];
        size_t o = ((size_t)(b * 512 + h * 64 + k)) * (size_t)L + (size_t)(l0 + t);
        out[ZQ_OFF + o] = c;
        float dd = zv - c;
        lsum += dd * dd;
        atomicAdd(&g_sums[(h * M + m) * D + k], zv);
    }

    // block-reduce loss -> one atomic per block
#pragma unroll
    for (int o = 16; o > 0; o >>= 1)
        lsum += __shfl_xor_sync(0xffffffffu, lsum, o);
    if ((tid & 31) == 0) s.red[tid >> 5] = lsum;
    __syncthreads();
    if (tid == 0) {
        float tt = 0.0f;
#pragma unroll
        for (int w = 0; w < 8; w++) tt += s.red[w];
        atomicAdd(&g_loss, tt);
    }
}

// ---------------------------------------------------------------------------
// Update kernel: slerp + rms_norm codebook EMA (1 warp per code) + vq_loss.
// ---------------------------------------------------------------------------
__global__ void vq_update(const float* __restrict__ cb, float* __restrict__ out) {
    if (blockIdx.x == 0 && threadIdx.x == 0) {
        // vq_loss = codebook_loss + 0.25*commitment_loss = 1.25 * MSE
        out[LOSS_OFF] = 1.25f * g_loss * (1.0f / 8388608.0f);
    }

    const int code = blockIdx.x * 8 + (threadIdx.x >> 5);
    const int lane = threadIdx.x & 31;
    if (code >= H * M) return;

    const float* old = cb + (size_t)code * D;
    float o0 = old[lane];
    float o1 = old[lane + 32];
    float cnt = g_counts[code];
    float r0, r1;

    if (cnt > 0.0f) {
        float m0 = g_sums[code * D + lane] / cnt;
        float m1 = g_sums[code * D + lane + 32] / cnt;

        float dot = m0 * o0 + m1 * o1;
        float nl  = m0 * m0 + m1 * m1;
        float nh  = o0 * o0 + o1 * o1;
#pragma unroll
        for (int o = 16; o > 0; o >>= 1) {
            dot += __shfl_xor_sync(0xffffffffu, dot, o);
            nl  += __shfl_xor_sync(0xffffffffu, nl,  o);
            nh  += __shfl_xor_sync(0xffffffffu, nh,  o);
        }
        float cosv = dot / fmaxf(sqrtf(nl) * sqrtf(nh), 1e-8f);
        cosv = fminf(fmaxf(cosv, (float)(-1.0 + 1e-7)), (float)(1.0 - 1e-7));
        float omega = acosf(cosv);
        float so = sinf(omega);
        float wl = sinf(0.01f * omega);   // (1 - decay) * omega
        float wh = sinf(0.99f * omega);   // decay * omega
        r0 = (m0 * wl + o0 * wh) / so;
        r1 = (m1 * wl + o1 * wh) / so;

        float ss = r0 * r0 + r1 * r1;
#pragma unroll
        for (int o = 16; o > 0; o >>= 1)
            ss += __shfl_xor_sync(0xffffffffu, ss, o);
        float inv = 1.0f / sqrtf(ss * (1.0f / 64.0f) + 1.1920929e-07f);
        r0 *= inv;
        r1 *= inv;
    } else {
        r0 = o0;
        r1 = o1;
    }

    out[CB_OFF + (size_t)code * D + lane]      = r0;
    out[CB_OFF + (size_t)code * D + lane + 32] = r1;
}

// ---------------------------------------------------------------------------
extern "C" void kernel_launch(void* const* d_in, const int* in_sizes, int n_in,
                              void* d_out, int out_size) {
    const float* z  = (const float*)d_in[0];   // [8, 512, 2048]
    const float* cb = (const float*)d_in[1];   // [8, 1024, 64]
    float* out = (float*)d_out;

    cudaFuncSetAttribute(vq_main, cudaFuncAttributeMaxDynamicSharedMemorySize,
                         (int)sizeof(Smem));

    dim3 grid(NTOK / TOK, H);
    vq_main<<<grid, 256, sizeof(Smem)>>>(z, cb, out);

    vq_update<<<H * M / 8, 256>>>(cb, out);

    // Reset scratch for the NEXT invocation (initial state is zero at load).
    zero_kernel<<<(H * M * D + 255) / 256, 256>>>();
}